// round 16
// baseline (speedup 1.0000x reference)
#include <cuda_runtime.h>
#include <cuda_fp16.h>

#define S3 0.86602540378443864676f   // sqrt(3)/2
typedef unsigned long long u64;

__device__ __forceinline__ void ffma2(u64 &d, u64 a, u64 b) {
    asm("fma.rn.f32x2 %0, %1, %2, %0;" : "+l"(d) : "l"(a), "l"(b));
}
__device__ __forceinline__ u64 mul2(u64 a, u64 b) {
    u64 r; asm("mul.rn.f32x2 %0, %1, %2;" : "=l"(r) : "l"(a), "l"(b)); return r;
}
__device__ __forceinline__ float2 u2f(u64 v) {
    float2 f; asm("mov.b64 {%0,%1}, %2;" : "=f"(f.x), "=f"(f.y) : "l"(v)); return f;
}
__device__ __forceinline__ u64 pack2(float lo, float hi) {
    u64 r; asm("mov.b64 %0, {%1,%2};" : "=l"(r) : "f"(lo), "f"(hi)); return r;
}

// ---------------- scratch ----------------
__device__ float2 g_X[1024*256];        // [mode][b*32+i]
__device__ unsigned int g_Wh[1024*1024];// [mode][i*32+o]  half2(1024*w)
__device__ float2 g_Y[8*32*16*32*2];    // [bo][kx][kt][kz]  (scaled x1024)
__device__ float4 g_T5q[16*64];         // [kx][q] (c,c,s,s)  th = 2pi q kx/256

// ---------------- kAC: fused [x-DFT + t-DFT + p-rfft] + weight prep -------
// blocks 0..255: kA (bi = blk); blocks 256..511: weight transpose; 512: T5q
// dyn smem (kA): A_sh 6144 f2 (49152 B) + staging 6272 u64 (50176 B) = 99328 B
__global__ void __launch_bounds__(384, 2) kAC_fwd(
        const float* __restrict__ x,
        const float* __restrict__ w1re, const float* __restrict__ w1im,
        const float* __restrict__ w2re, const float* __restrict__ w2im) {
    extern __shared__ float2 smem[];
    int blk = blockIdx.x, tid = threadIdx.x;

    if (blk >= 256) {
        int b2 = blk - 256;
        if (b2 < 256) {
            unsigned int* t1 = (unsigned int*)smem;
            unsigned int* t2 = t1 + 64*33;
            int io0 = (b2 >> 3) * 32, e0i = (b2 & 7) * 64;
            if (tid < 256) {
                int el = tid & 63, iol = tid >> 6;
                int e = e0i + el;
                int ktw = e >> 5, kx = (e >> 1) & 15, kz = e & 1;
                int off = ktw*48 + kx*3 + kz;
                #pragma unroll
                for (int pass = 0; pass < 8; pass++) {
                    int il = pass*4 + iol;
                    int s = (io0 + il)*768 + off;
                    __half2 h1 = __floats2half2_rn(w1re[s]*1024.f, w1im[s]*1024.f);
                    __half2 h2 = __floats2half2_rn(w2re[s]*1024.f, w2im[s]*1024.f);
                    t1[el*33 + il] = *reinterpret_cast<unsigned int*>(&h1);
                    t2[el*33 + il] = *reinterpret_cast<unsigned int*>(&h2);
                }
            }
            __syncthreads();
            if (tid < 256) {
                int il2 = tid & 31;
                #pragma unroll
                for (int pass = 0; pass < 8; pass++) {
                    int el2 = pass*8 + (tid >> 5);
                    g_Wh[(size_t)(e0i + el2)*1024 + io0 + il2]       = t1[el2*33 + il2];
                    g_Wh[(size_t)(e0i + el2 + 512)*1024 + io0 + il2] = t2[el2*33 + il2];
                }
            }
        } else {
            if (tid < 256)
                for (int i = tid; i < 1024; i += 256) {
                    int kx = i >> 6, q = i & 63;
                    float s, c; sincospif((float)(q*kx) * (1.0f/128.0f), &s, &c);
                    g_T5q[i] = make_float4(c, c, s, s);
                }
        }
        return;
    }

    // =================== kA body ===================
    float2* A_sh = smem;                 // [kx][p][t] 16*3*128
    u64* SB  = (u64*)(smem + 6144);
    u64* E0  = SB;                       // [tp][p][q<64] pitch 198 (3*66)
    u64* E2  = SB + 1584;
    u64* DAB = SB + 3168;                // [tp][q*3+p] ulonglong2, pitch 194
    int bi = blk;

    int w = tid >> 5, lane = tid & 31;
    int cls = w & 3, p = w >> 2;
    int j = lane >> 3, tp = lane & 7;
    int kx = cls + 4*j;

    // per-thread constants: omega = e^{-i pi kx/128}; omega^2 rotator
    float rs_, rc_; sincospif((float)kx * (1.0f/128.0f), &rs_, &rc_);
    float rs2_, rc2_; sincospif((float)kx * (1.0f/64.0f), &rs2_, &rc2_);
    u64 RC2 = pack2(rc2_, rc2_), RS2 = pack2(rs2_, rs2_), NRS2 = pack2(-rs2_, -rs2_);
    #define ROT2() { u64 t_ = mul2(CC, RC2); ffma2(t_, SS, NRS2); \
                     u64 u_ = mul2(SS, RC2); ffma2(u_, CC, RS2);  \
                     CC = t_; SS = u_; }

    int tpp = tid / 48;
    int r4 = (tid - tpp*48) * 4;
    const float* sbase = x + (size_t)bi*128*768 + 2*tpp*768 + r4;

    float4 a0, a1, a2, a3, b0, b1, b2, b3;
    #define LOADP(c) { const float* s0_ = sbase + (c)*16*768; \
        a0 = *(const float4*)(s0_);        a1 = *(const float4*)(s0_ + 192); \
        a2 = *(const float4*)(s0_ + 384);  a3 = *(const float4*)(s0_ + 576); \
        b0 = *(const float4*)(s0_ + 768);  b1 = *(const float4*)(s0_ + 960); \
        b2 = *(const float4*)(s0_ + 1152); b3 = *(const float4*)(s0_ + 1344); }

    LOADP(0)

    // ---- phase 1: x-DFT radix-4, parity-split shared rotator ------------
    for (int chunk = 0; chunk < 8; chunk++) {
        {   // fold prefetched registers -> staging
            u64 e0v[4], e2v[4], dav[4], dbv[4];
            #define FOLD(jj, xa0, xa1, xa2, xa3, xb0, xb1, xb2, xb3) { \
                float s02a = (xa0) + (xa2), s13a = (xa1) + (xa3);      \
                float s02b = (xb0) + (xb2), s13b = (xb1) + (xb3);      \
                e0v[jj] = pack2(s02a + s13a, s02b + s13b);             \
                e2v[jj] = pack2(s02a - s13a, s02b - s13b);             \
                dav[jj] = pack2((xa0) - (xa2), (xb0) - (xb2));         \
                dbv[jj] = pack2((xa1) - (xa3), (xb1) - (xb3)); }
            FOLD(0, a0.x, a1.x, a2.x, a3.x, b0.x, b1.x, b2.x, b3.x)
            FOLD(1, a0.y, a1.y, a2.y, a3.y, b0.y, b1.y, b2.y, b3.y)
            FOLD(2, a0.z, a1.z, a2.z, a3.z, b0.z, b1.z, b2.z, b3.z)
            FOLD(3, a0.w, a1.w, a2.w, a3.w, b0.w, b1.w, b2.w, b3.w)
            #undef FOLD
            #pragma unroll
            for (int jj = 0; jj < 4; jj++) {       // E0/E2 scatter [tp][p][q]
                int r = r4 + jj;
                int q = r / 3, pz = r - q*3;
                E0[tpp*198 + pz*66 + q] = e0v[jj];
                E2[tpp*198 + pz*66 + q] = e2v[jj];
            }
            int bx = tpp*194 + r4;
            *(ulonglong2*)&DAB[2*bx]     = make_ulonglong2(dav[0], dbv[0]);
            *(ulonglong2*)&DAB[2*bx + 2] = make_ulonglong2(dav[1], dbv[1]);
            *(ulonglong2*)&DAB[2*bx + 4] = make_ulonglong2(dav[2], dbv[2]);
            *(ulonglong2*)&DAB[2*bx + 6] = make_ulonglong2(dav[3], dbv[3]);
        }
        __syncthreads();
        if (chunk < 7) LOADP(chunk + 1)
        int t0 = chunk*16 + tp*2;
        if ((cls & 1) == 0) {
            const u64* plane = (cls == 0 ? E0 : E2) + tp*198 + p*66;
            u64 R0=0, I0=0, R1=0, I1=0;
            #pragma unroll
            for (int g = 0; g < 4; g++) {
                float sg_, cg_; sincospif((float)(g*kx) * 0.125f, &sg_, &cg_);
                u64 CC = pack2(cg_, cg_), SS = pack2(sg_, sg_);
                #pragma unroll
                for (int kk = 0; kk < 8; kk++) {
                    ulonglong2 v = *(const ulonglong2*)&plane[g*16 + kk*2];
                    ffma2(R0, v.x, CC); ffma2(I0, v.x, SS);
                    ffma2(R1, v.y, CC); ffma2(I1, v.y, SS);
                    if (kk != 7) ROT2();
                }
            }
            float2 r0f = u2f(R0), i0f = u2f(I0), r1f = u2f(R1), i1f = u2f(I1);
            // S = S0 + e^{-i th} S1, e^{-i th} = (rc_, -rs_)
            float reA = r0f.x + rc_*r1f.x - rs_*i1f.x;
            float imA = i0f.x + rc_*i1f.x + rs_*r1f.x;
            float reB = r0f.y + rc_*r1f.y - rs_*i1f.y;
            float imB = i0f.y + rc_*i1f.y + rs_*r1f.y;
            *(float4*)(A_sh + (kx*3 + p)*128 + t0) = make_float4(reA, -imA, reB, -imB);
        } else {
            const ulonglong2* rab = (const ulonglong2*)DAB + tp*194;
            u64 RA0=0,IA0=0,RB0=0,IB0=0, RA1=0,IA1=0,RB1=0,IB1=0;
            #pragma unroll
            for (int g = 0; g < 4; g++) {
                float sg_, cg_; sincospif((float)(g*kx) * 0.125f, &sg_, &cg_);
                u64 CC = pack2(cg_, cg_), SS = pack2(sg_, sg_);
                #pragma unroll
                for (int kk = 0; kk < 8; kk++) {
                    ulonglong2 v0 = rab[(g*16 + kk*2)*3 + p];
                    ulonglong2 v1 = rab[(g*16 + kk*2 + 1)*3 + p];
                    ffma2(RA0, v0.x, CC); ffma2(IA0, v0.x, SS);
                    ffma2(RB0, v0.y, SS); ffma2(IB0, v0.y, CC);
                    ffma2(RA1, v1.x, CC); ffma2(IA1, v1.x, SS);
                    ffma2(RB1, v1.y, SS); ffma2(IB1, v1.y, CC);
                    if (kk != 7) ROT2();
                }
            }
            float sg = (cls == 1) ? -1.f : 1.f;   // class1: b=-d13; class3: b=+d13
            float2 rA0 = u2f(RA0), iA0 = u2f(IA0), rB0 = u2f(RB0), iB0 = u2f(IB0);
            float2 rA1 = u2f(RA1), iA1 = u2f(IA1), rB1 = u2f(RB1), iB1 = u2f(IB1);
            float o4[4];
            #pragma unroll
            for (int h = 0; h < 2; h++) {
                float sxe = h ? rA0.y + sg*rB0.y : rA0.x + sg*rB0.x;
                float sye = h ? sg*iB0.y - iA0.y : sg*iB0.x - iA0.x;
                float sxo = h ? rA1.y + sg*rB1.y : rA1.x + sg*rB1.x;
                float syo = h ? sg*iB1.y - iA1.y : sg*iB1.x - iA1.x;
                o4[h*2 + 0] = sxe + rc_*sxo + rs_*syo;
                o4[h*2 + 1] = sye + rc_*syo - rs_*sxo;
            }
            *(float4*)(A_sh + (kx*3 + p)*128 + t0) = make_float4(o4[0], o4[1], o4[2], o4[3]);
        }
        __syncthreads();
    }
    #undef LOADP
    #undef ROT2

    // ---- phase 2: t-DFT radix-4 + p-rfft --------------------------------
    float2* Ys = smem + 6144;     // 16*384, aliases staging
    float2* Xt = A_sh;            // aliases dead A_sh
    for (int idx = tid; idx < 1536; idx += 384) {         // class build
        int kxx = idx / 96, r = idx - kxx*96;
        int pp = r >> 5, q = r & 31;
        const float2* Ap = A_sh + kxx*384 + pp*128;
        float2 A0 = Ap[q], A1 = Ap[q + 32], A2 = Ap[q + 64], A3 = Ap[q + 96];
        float Dx = A0.x - A2.x, Dy = A0.y - A2.y;
        float Ex = A1.x - A3.x, Ey = A1.y - A3.y;
        float2* Yk = Ys + kxx*384;
        Yk[(0*3 + pp)*32 + q] = make_float2(A0.x+A1.x+A2.x+A3.x, A0.y+A1.y+A2.y+A3.y);
        Yk[(1*3 + pp)*32 + q] = make_float2(Dx + Ey, Dy - Ex);
        Yk[(2*3 + pp)*32 + q] = make_float2(A0.x-A1.x+A2.x-A3.x, A0.y-A1.y+A2.y-A3.y);
        Yk[(3*3 + pp)*32 + q] = make_float2(Dx - Ey, Dy + Ex);
    }
    __syncthreads();
    for (int idx = tid; idx < 1536; idx += 384) {         // mode dot products (rotator)
        int kxx = idx / 96, r = idx - kxx*96;
        int kt = r & 31, pp = r >> 5;
        int ktg = kt + ((kt >= 16) ? 96 : 0);
        float rs2, rc2; sincospif((float)ktg * (1.0f/64.0f), &rs2, &rc2);
        const float2* Yp = Ys + kxx*384 + ((kt & 3)*3 + pp)*32;
        float re = 0.f, im = 0.f;
        float cc = 1.f, ss = 0.f;
        #pragma unroll
        for (int q = 0; q < 32; q++) {
            float2 y = Yp[q];
            re += y.x*cc + y.y*ss;
            im += y.y*cc - y.x*ss;
            float nc = cc*rc2 - ss*rs2;
            ss = ss*rc2 + cc*rs2;
            cc = nc;
        }
        Xt[(kxx*32 + kt)*3 + pp] = make_float2(re, im);
    }
    __syncthreads();
    for (int idx = tid; idx < 1024; idx += 384) {         // p-rfft + store
        int kxx = idx >> 6, r = idx & 63;
        int kt = r & 31, kz = r >> 5;
        const float2* Xp = Xt + (kxx*32 + kt)*3;
        float2 a0f = Xp[0], a1f = Xp[1], a2f = Xp[2];
        float2 rr;
        if (kz == 0) rr = make_float2(a0f.x + a1f.x + a2f.x, a0f.y + a1f.y + a2f.y);
        else rr = make_float2(a0f.x - 0.5f*(a1f.x + a2f.x) + S3*(a1f.y - a2f.y),
                              a0f.y - 0.5f*(a1f.y + a2f.y) - S3*(a1f.x - a2f.x));
        g_X[(size_t)((kt*16 + kxx)*2 + kz)*256 + bi] = rr;
    }
}

// ---------------- k3: per-mode complex GEMM (fp16 weights) ----------------
__global__ void k3_mix() {
    __shared__ float2 Xs[256];
    __shared__ float2 Ws[1024];
    int mode = blockIdx.x, tid = threadIdx.x;
    Xs[tid] = g_X[(size_t)mode*256 + tid];
    {
        uint4 wv = ((const uint4*)(g_Wh + (size_t)mode*1024))[tid];
        __half2 h;
        h = *reinterpret_cast<__half2*>(&wv.x); Ws[tid*4 + 0] = __half22float2(h);
        h = *reinterpret_cast<__half2*>(&wv.y); Ws[tid*4 + 1] = __half22float2(h);
        h = *reinterpret_cast<__half2*>(&wv.z); Ws[tid*4 + 2] = __half22float2(h);
        h = *reinterpret_cast<__half2*>(&wv.w); Ws[tid*4 + 3] = __half22float2(h);
    }
    __syncthreads();
    int b = tid >> 5, o = tid & 31;
    float re0=0, im0=0, re1=0, im1=0;
    #pragma unroll
    for (int i = 0; i < 32; i += 2) {
        float2 xv = Xs[b*32 + i];     float2 wv = Ws[i*32 + o];
        re0 += xv.x*wv.x - xv.y*wv.y; im0 += xv.x*wv.y + xv.y*wv.x;
        float2 xq = Xs[b*32 + i + 1]; float2 wq = Ws[(i+1)*32 + o];
        re1 += xq.x*wq.x - xq.y*wq.y; im1 += xq.x*wq.y + xq.y*wq.x;
    }
    int kz = mode & 1, kx = (mode >> 1) & 15, kt = mode >> 5;
    g_Y[(size_t)(((b*32 + o)*16 + kx)*32 + kt)*2 + kz] = make_float2(re0+re1, im0+im1);
}

// ---------------- kB: fused U-build + t-expand + x-expand -----------------
// grid 256 = bo; block 576 (18 warps), 2 blocks/SM
// dyn smem (f2): Y 1024 | U 1536 | Vq 6272 | Tsh 512 = 9344 f2 = 74752 B
__global__ void __launch_bounds__(576, 2) kB_inv(float* __restrict__ out) {
    extern __shared__ float2 smem[];
    float2* Y_sh = smem;                          // [kx*64 + kt*2 + kz]
    float2* U_sh = smem + 1024;                   // [kx*96 + kt*3 + p]
    ulonglong2* Vq = (ulonglong2*)(smem + 2560);  // [pr*49 + kx*3 + p] = (vx01, vy01)
    ulonglong2* Tsh = (ulonglong2*)(smem + 8832); // [c-1][q] c=1..4  (cc,ss packed)
    int bo = blockIdx.x, tid = threadIdx.x;

    for (int idx = tid; idx < 512; idx += 576)
        ((float4*)Y_sh)[idx] = ((const float4*)(g_Y + (size_t)bo*1024))[idx];
    for (int idx = tid; idx < 256; idx += 576)
        Tsh[idx] = ((const ulonglong2*)g_T5q)[64 + idx];       // rows kx=1..4
    __syncthreads();

    // B2: build U  (SC folds the fp16 x1024 weight scale)
    for (int idx = tid; idx < 1536; idx += 576) {
        int kx = idx / 96, r = idx - kx*96;
        int kt = r & 31, p = r >> 5;
        float2 y0 = Y_sh[kx*64 + kt*2], y1 = Y_sh[kx*64 + kt*2 + 1];
        float wx, wy;                          // 2 * e^{2 pi i p / 3}
        if (p == 0)      { wx = 2.f;  wy = 0.f; }
        else if (p == 1) { wx = -1.f; wy =  2.f*S3; }
        else             { wx = -1.f; wy = -2.f*S3; }
        const float SC = 1.f/100663296.f;      // 1/(128*256*3*1024)
        U_sh[kx*96 + kt*3 + p] = make_float2(SC*(y0.x + wx*y1.x - wy*y1.y),
                                             SC*(y0.y + wx*y1.y + wy*y1.x));
    }
    __syncthreads();

    // B3: t-expand radix-4 -> Vq via per-q Horner (no T4 loads)
    for (int idx = tid; idx < 1536; idx += 576) {
        int kx = idx / 96, r = idx - kx*96;
        int q = r & 31, p = r >> 5;
        float rs, rc;  sincospif((float)q * 0.0625f,   &rs, &rc);    // rho = e^{i pi q/16}
        float ts1, tc1; sincospif((float)q * 0.015625f, &ts1, &tc1); // tau = e^{i pi q/64}
        float r4s, r4c; sincospif((float)q * 0.25f,     &r4s, &r4c); // rho^4
        float kr, ki;                          // kappa = (-i)^q * rho^4
        switch (q & 3) {
            case 0: kr = r4c;  ki = r4s;  break;
            case 1: kr = r4s;  ki = -r4c; break;
            case 2: kr = -r4c; ki = -r4s; break;
            default:kr = -r4s; ki = r4c;  break;
        }
        float t2c = tc1*tc1 - ts1*ts1, t2s = 2.f*tc1*ts1;
        float t3c = t2c*tc1 - t2s*ts1, t3s = t2s*tc1 + t2c*ts1;
        const float2* Ub = U_sh + kx*96 + p;
        float Sx[4], Sy[4];
        #pragma unroll
        for (int c = 0; c < 4; c++) {
            float2 u = Ub[(c + 28)*3];
            float hx = u.x, hy = u.y;
            #pragma unroll
            for (int m = 6; m >= 4; m--) {
                u = Ub[(c + 4*m)*3];
                float nx = u.x + rc*hx - rs*hy;
                float ny = u.y + rc*hy + rs*hx;
                hx = nx; hy = ny;
            }
            float hix = hx, hiy = hy;
            u = Ub[(c + 12)*3];
            hx = u.x; hy = u.y;
            #pragma unroll
            for (int m = 2; m >= 0; m--) {
                u = Ub[(c + 4*m)*3];
                float nx = u.x + rc*hx - rs*hy;
                float ny = u.y + rc*hy + rs*hx;
                hx = nx; hy = ny;
            }
            float sx = hx + kr*hix - ki*hiy;
            float sy = hy + kr*hiy + ki*hix;
            if (c == 1)      { float tx = sx*tc1 - sy*ts1; sy = sx*ts1 + sy*tc1; sx = tx; }
            else if (c == 2) { float tx = sx*t2c - sy*t2s; sy = sx*t2s + sy*t2c; sx = tx; }
            else if (c == 3) { float tx = sx*t3c - sy*t3s; sy = sx*t3s + sy*t3c; sx = tx; }
            Sx[c] = sx; Sy[c] = sy;
        }
        float s0x = Sx[0], s0y = Sy[0], s1x = Sx[1], s1y = Sy[1];
        float s2x = Sx[2], s2y = Sy[2], s3x = Sx[3], s3y = Sy[3];
        float vr[4], vi[4];
        vr[0] = s0x+s1x+s2x+s3x; vi[0] = s0y+s1y+s2y+s3y;
        vr[1] = s0x-s1y-s2x+s3y; vi[1] = s0y+s1x-s2y-s3x;
        vr[2] = s0x-s1x+s2x-s3x; vi[2] = s0y-s1y+s2y-s3y;
        vr[3] = s0x+s1y-s2x-s3y; vi[3] = s0y-s1x-s2y+s3x;
        int h = q & 1;
        float* base = (float*)Vq;
        #pragma unroll
        for (int m = 0; m < 4; m++) {
            int pr = (q >> 1) + 16*m;
            int e4 = (pr*49 + kx*3 + p)*4;
            base[e4 + h]     = vr[m];
            base[e4 + 2 + h] = vi[m];
        }
    }
    __syncthreads();

    // B4: x-expand radix-4 via Horner (no in-loop twiddle loads)
    {
        int ee = tid % 192, prh = tid / 192;      // prh in 0..2 (576 = 3*192)
        int q = ee / 3, p = ee - q*3;
        ulonglong2 Rv = Tsh[192 + q];             // kx=4 row: phi = pi q/32
        u64 RC = Rv.x, RS = Rv.y;
        float2 rsf = u2f(RS);
        u64 NRS = pack2(-rsf.x, -rsf.y);
        float tc1 = u2f(Tsh[q].x).x,       ts1 = u2f(Tsh[q].y).x;
        float tc2 = u2f(Tsh[64 + q].x).x,  ts2 = u2f(Tsh[64 + q].y).x;
        float tc3 = u2f(Tsh[128 + q].x).x, ts3 = u2f(Tsh[128 + q].y).x;

        for (int pr = prh; pr < 64; pr += 3) {
            const ulonglong2* vrow = Vq + pr*49 + p;
            u64 W0x, W0y, W1x, W1y, W2x, W2y, W3x, W3y;
            { ulonglong2 v = vrow[12*3]; W0x = v.x; W0y = v.y; }
            { ulonglong2 v = vrow[13*3]; W1x = v.x; W1y = v.y; }
            { ulonglong2 v = vrow[14*3]; W2x = v.x; W2y = v.y; }
            { ulonglong2 v = vrow[15*3]; W3x = v.x; W3y = v.y; }
            #define HSTEP(c, jj) { \
                ulonglong2 v = vrow[((c) + 4*(jj))*3]; \
                u64 t_ = v.x; ffma2(t_, W##c##x, RC); ffma2(t_, W##c##y, NRS); \
                u64 u_ = v.y; ffma2(u_, W##c##x, RS); ffma2(u_, W##c##y, RC);  \
                W##c##x = t_; W##c##y = u_; }
            HSTEP(0, 2) HSTEP(1, 2) HSTEP(2, 2) HSTEP(3, 2)
            HSTEP(0, 1) HSTEP(1, 1) HSTEP(2, 1) HSTEP(3, 1)
            HSTEP(0, 0) HSTEP(1, 0) HSTEP(2, 0) HSTEP(3, 0)
            #undef HSTEP
            float2 W0xf = u2f(W0x);
            float2 W1xf = u2f(W1x), W1yf = u2f(W1y);
            float2 W2xf = u2f(W2x), W2yf = u2f(W2y);
            float2 W3xf = u2f(W3x), W3yf = u2f(W3y);
            float* r0 = out + ((size_t)bo*128 + pr*2)*768;
            float* r1 = r0 + 768;
            #pragma unroll
            for (int h = 0; h < 2; h++) {
                float w0x = h ? W0xf.y : W0xf.x;
                float w1x = h ? W1xf.y : W1xf.x, w1y = h ? W1yf.y : W1yf.x;
                float w2x = h ? W2xf.y : W2xf.x, w2y = h ? W2yf.y : W2yf.x;
                float w3x = h ? W3xf.y : W3xf.x, w3y = h ? W3yf.y : W3yf.x;
                float tr0 = w0x;
                float tr1 = w1x*tc1 - w1y*ts1;
                float ti1 = w1x*ts1 + w1y*tc1;
                float tr2 = w2x*tc2 - w2y*ts2;
                float tr3 = w3x*tc3 - w3y*ts3;
                float ti3 = w3x*ts3 + w3y*tc3;
                float ev = tr0 + tr2, fv = tr0 - tr2;
                float g1 = tr1 + tr3, dti = ti3 - ti1;
                float* row = h ? r1 : r0;
                row[(q      )*3 + p] = ev + g1;
                row[(q + 64 )*3 + p] = fv + dti;
                row[(q + 128)*3 + p] = ev - g1;
                row[(q + 192)*3 + p] = fv - dti;
            }
        }
    }
}

extern "C" void kernel_launch(void* const* d_in, const int* in_sizes, int n_in,
                              void* d_out, int out_size) {
    const float* x    = (const float*)d_in[0];
    const float* w1re = (const float*)d_in[1];
    const float* w1im = (const float*)d_in[2];
    const float* w2re = (const float*)d_in[3];
    const float* w2im = (const float*)d_in[4];
    float* out = (float*)d_out;

    static int attr_done = 0;
    if (!attr_done) {
        cudaFuncSetAttribute(kAC_fwd, cudaFuncAttributeMaxDynamicSharedMemorySize, 99328);
        cudaFuncSetAttribute(kB_inv, cudaFuncAttributeMaxDynamicSharedMemorySize, 74752);
        attr_done = 1;
    }

    kAC_fwd<<<513, 384, 99328>>>(x, w1re, w1im, w2re, w2im);
    k3_mix<<<1024, 256>>>();
    kB_inv<<<256, 576, 74752>>>(out);
}

// round 17
// speedup vs baseline: 1.0639x; 1.0639x over previous
#include <cuda_runtime.h>
#include <cuda_fp16.h>

#define S3 0.86602540378443864676f   // sqrt(3)/2
typedef unsigned long long u64;

__device__ __forceinline__ void ffma2(u64 &d, u64 a, u64 b) {
    asm("fma.rn.f32x2 %0, %1, %2, %0;" : "+l"(d) : "l"(a), "l"(b));
}
__device__ __forceinline__ u64 mul2(u64 a, u64 b) {
    u64 r; asm("mul.rn.f32x2 %0, %1, %2;" : "=l"(r) : "l"(a), "l"(b)); return r;
}
__device__ __forceinline__ float2 u2f(u64 v) {
    float2 f; asm("mov.b64 {%0,%1}, %2;" : "=f"(f.x), "=f"(f.y) : "l"(v)); return f;
}
__device__ __forceinline__ u64 pack2(float lo, float hi) {
    u64 r; asm("mov.b64 %0, {%1,%2};" : "=l"(r) : "f"(lo), "f"(hi)); return r;
}

// ---------------- scratch ----------------
__device__ float2 g_X[1024*256];        // [mode][b*32+i]
__device__ unsigned int g_Wh[1024*1024];// [mode][i*32+o]  half2(1024*w)
__device__ float2 g_Y[8*32*16*32*2];    // [bo][kx][kt][kz]  (scaled x1024)
__device__ float4 g_T5q[16*64];         // [kx][q] (c,c,s,s)  th = 2pi q kx/256

// rotate packed (CC,SS) by (RC,RS)
#define ROT() { u64 t_ = mul2(CC, RC); ffma2(t_, SS, NRS); \
                u64 u_ = mul2(SS, RC); ffma2(u_, CC, RS);  \
                CC = t_; SS = u_; }

// ---------------- kAC: fused [x-DFT + t-DFT + p-rfft] + weight prep -------
// blocks 0..255: kA (bi = blk); blocks 256..511: weight transpose; 512: T5q
// dyn smem (kA): A_sh 6144 f2 (49152 B) + staging 6208 u64 (49664 B) = 98816 B
__global__ void __launch_bounds__(384, 2) kAC_fwd(
        const float* __restrict__ x,
        const float* __restrict__ w1re, const float* __restrict__ w1im,
        const float* __restrict__ w2re, const float* __restrict__ w2im) {
    extern __shared__ float2 smem[];
    int blk = blockIdx.x, tid = threadIdx.x;

    if (blk >= 256) {
        int b2 = blk - 256;
        if (b2 < 256) {
            unsigned int* t1 = (unsigned int*)smem;
            unsigned int* t2 = t1 + 64*33;
            int io0 = (b2 >> 3) * 32, e0i = (b2 & 7) * 64;
            if (tid < 256) {
                int el = tid & 63, iol = tid >> 6;
                int e = e0i + el;
                int ktw = e >> 5, kx = (e >> 1) & 15, kz = e & 1;
                int off = ktw*48 + kx*3 + kz;
                #pragma unroll
                for (int pass = 0; pass < 8; pass++) {
                    int il = pass*4 + iol;
                    int s = (io0 + il)*768 + off;
                    __half2 h1 = __floats2half2_rn(w1re[s]*1024.f, w1im[s]*1024.f);
                    __half2 h2 = __floats2half2_rn(w2re[s]*1024.f, w2im[s]*1024.f);
                    t1[el*33 + il] = *reinterpret_cast<unsigned int*>(&h1);
                    t2[el*33 + il] = *reinterpret_cast<unsigned int*>(&h2);
                }
            }
            __syncthreads();
            if (tid < 256) {
                int il2 = tid & 31;
                #pragma unroll
                for (int pass = 0; pass < 8; pass++) {
                    int el2 = pass*8 + (tid >> 5);
                    g_Wh[(size_t)(e0i + el2)*1024 + io0 + il2]       = t1[el2*33 + il2];
                    g_Wh[(size_t)(e0i + el2 + 512)*1024 + io0 + il2] = t2[el2*33 + il2];
                }
            }
        } else {
            if (tid < 256)
                for (int i = tid; i < 1024; i += 256) {
                    int kx = i >> 6, q = i & 63;
                    float s, c; sincospif((float)(q*kx) * (1.0f/128.0f), &s, &c);
                    g_T5q[i] = make_float4(c, c, s, s);
                }
        }
        return;
    }

    // =================== kA body ===================
    float2* A_sh = smem;                 // [kx][p][t] 16*3*128
    u64* SB  = (u64*)(smem + 6144);
    u64* E0  = SB;                       // 1552 (pitch 194 u64, ≡16 mod 128 B)
    u64* E2  = SB + 1552;                // 1552
    u64* DAB = SB + 3104;                // 3088 (pitch 193 ulonglong2, ≡16 mod 128 B)
    int bi = blk;

    int w = tid >> 5, lane = tid & 31;
    int cls = w & 3, p = w >> 2;
    int j = lane >> 3, tp = lane & 7;
    int kx = cls + 4*j;

    // per-thread rotator: step angle 2*pi*kx/256 = pi*kx/128
    float rs_, rc_; sincospif((float)kx * (1.0f/128.0f), &rs_, &rc_);
    u64 RC = pack2(rc_, rc_), RS = pack2(rs_, rs_), NRS = pack2(-rs_, -rs_);

    int tpp = tid / 48;
    int r4 = (tid - tpp*48) * 4;
    const float* sbase = x + (size_t)bi*128*768 + 2*tpp*768 + r4;

    float4 a0, a1, a2, a3, b0, b1, b2, b3;
    #define LOADP(c) { const float* s0_ = sbase + (c)*16*768; \
        a0 = *(const float4*)(s0_);        a1 = *(const float4*)(s0_ + 192); \
        a2 = *(const float4*)(s0_ + 384);  a3 = *(const float4*)(s0_ + 576); \
        b0 = *(const float4*)(s0_ + 768);  b1 = *(const float4*)(s0_ + 960); \
        b2 = *(const float4*)(s0_ + 1152); b3 = *(const float4*)(s0_ + 1344); }

    LOADP(0)

    // ---- phase 1: x-DFT radix-4, prefetch-pipelined ---------------------
    for (int chunk = 0; chunk < 8; chunk++) {
        {   // fold prefetched registers -> staging
            u64 e0v[4], e2v[4], dav[4], dbv[4];
            #define FOLD(jj, xa0, xa1, xa2, xa3, xb0, xb1, xb2, xb3) { \
                float s02a = (xa0) + (xa2), s13a = (xa1) + (xa3);      \
                float s02b = (xb0) + (xb2), s13b = (xb1) + (xb3);      \
                e0v[jj] = pack2(s02a + s13a, s02b + s13b);             \
                e2v[jj] = pack2(s02a - s13a, s02b - s13b);             \
                dav[jj] = pack2((xa0) - (xa2), (xb0) - (xb2));         \
                dbv[jj] = pack2((xa1) - (xa3), (xb1) - (xb3)); }
            FOLD(0, a0.x, a1.x, a2.x, a3.x, b0.x, b1.x, b2.x, b3.x)
            FOLD(1, a0.y, a1.y, a2.y, a3.y, b0.y, b1.y, b2.y, b3.y)
            FOLD(2, a0.z, a1.z, a2.z, a3.z, b0.z, b1.z, b2.z, b3.z)
            FOLD(3, a0.w, a1.w, a2.w, a3.w, b0.w, b1.w, b2.w, b3.w)
            #undef FOLD
            int bx = tpp*194 + r4;
            *(ulonglong2*)&E0[bx]       = make_ulonglong2(e0v[0], e0v[1]);
            *(ulonglong2*)&E0[bx + 2]   = make_ulonglong2(e0v[2], e0v[3]);
            *(ulonglong2*)&E2[bx]       = make_ulonglong2(e2v[0], e2v[1]);
            *(ulonglong2*)&E2[bx + 2]   = make_ulonglong2(e2v[2], e2v[3]);
            int bd = tpp*193 + r4;                 // conflict-free pitch (3088 B rows)
            *(ulonglong2*)&DAB[2*bd]     = make_ulonglong2(dav[0], dbv[0]);
            *(ulonglong2*)&DAB[2*bd + 2] = make_ulonglong2(dav[1], dbv[1]);
            *(ulonglong2*)&DAB[2*bd + 4] = make_ulonglong2(dav[2], dbv[2]);
            *(ulonglong2*)&DAB[2*bd + 6] = make_ulonglong2(dav[3], dbv[3]);
        }
        __syncthreads();
        if (chunk < 7) LOADP(chunk + 1)    // overlap next chunk's LDGs with compute
        int t0 = chunk*16 + tp*2;
        if ((cls & 1) == 0) {
            const u64* row = (cls == 0 ? E0 : E2) + tp*194;
            u64 R = 0, I = 0;
            #pragma unroll
            for (int g = 0; g < 4; g++) {
                float sg_, cg_; sincospif((float)(g*kx) * 0.125f, &sg_, &cg_);
                u64 CC = pack2(cg_, cg_), SS = pack2(sg_, sg_);
                #pragma unroll
                for (int qq = 0; qq < 16; qq++) {
                    u64 v = row[(g*16 + qq)*3 + p];
                    ffma2(R, v, CC); ffma2(I, v, SS);
                    if (qq != 15) ROT();
                }
            }
            float2 r = u2f(R), i = u2f(I);
            *(float4*)(A_sh + (kx*3 + p)*128 + t0) = make_float4(r.x, -i.x, r.y, -i.y);
        } else {
            const ulonglong2* rab = (const ulonglong2*)DAB + tp*193;
            u64 RA=0, IA=0, RB=0, IB=0;
            #pragma unroll
            for (int g = 0; g < 4; g++) {
                float sg_, cg_; sincospif((float)(g*kx) * 0.125f, &sg_, &cg_);
                u64 CC = pack2(cg_, cg_), SS = pack2(sg_, sg_);
                #pragma unroll
                for (int qq = 0; qq < 16; qq++) {
                    ulonglong2 vab = rab[(g*16 + qq)*3 + p];
                    ffma2(RA, vab.x, CC);
                    ffma2(IA, vab.x, SS);
                    ffma2(RB, vab.y, SS);
                    ffma2(IB, vab.y, CC);
                    if (qq != 15) ROT();
                }
            }
            float sg = (cls == 1) ? -1.f : 1.f;   // class1: b=-d13; class3: b=+d13
            float2 rA = u2f(RA), rB = u2f(RB), iA = u2f(IA), iB = u2f(IB);
            *(float4*)(A_sh + (kx*3 + p)*128 + t0) =
                make_float4(rA.x + sg*rB.x, sg*iB.x - iA.x,
                            rA.y + sg*rB.y, sg*iB.y - iA.y);
        }
        __syncthreads();
    }
    #undef LOADP

    // ---- phase 2: t-DFT radix-4 + p-rfft --------------------------------
    float2* Ys = smem + 6144;     // 16*384, aliases staging
    float2* Xt = A_sh;            // aliases dead A_sh
    for (int idx = tid; idx < 1536; idx += 384) {         // class build
        int kxx = idx / 96, r = idx - kxx*96;
        int pp = r >> 5, q = r & 31;
        const float2* Ap = A_sh + kxx*384 + pp*128;
        float2 A0 = Ap[q], A1 = Ap[q + 32], A2 = Ap[q + 64], A3 = Ap[q + 96];
        float Dx = A0.x - A2.x, Dy = A0.y - A2.y;
        float Ex = A1.x - A3.x, Ey = A1.y - A3.y;
        float2* Yk = Ys + kxx*384;
        Yk[(0*3 + pp)*32 + q] = make_float2(A0.x+A1.x+A2.x+A3.x, A0.y+A1.y+A2.y+A3.y);
        Yk[(1*3 + pp)*32 + q] = make_float2(Dx + Ey, Dy - Ex);
        Yk[(2*3 + pp)*32 + q] = make_float2(A0.x-A1.x+A2.x-A3.x, A0.y-A1.y+A2.y-A3.y);
        Yk[(3*3 + pp)*32 + q] = make_float2(Dx - Ey, Dy + Ex);
    }
    __syncthreads();
    for (int idx = tid; idx < 1536; idx += 384) {         // mode dot products (rotator)
        int kxx = idx / 96, r = idx - kxx*96;
        int kt = r & 31, pp = r >> 5;
        int ktg = kt + ((kt >= 16) ? 96 : 0);
        float rs2, rc2; sincospif((float)ktg * (1.0f/64.0f), &rs2, &rc2);
        const float2* Yp = Ys + kxx*384 + ((kt & 3)*3 + pp)*32;
        float re = 0.f, im = 0.f;
        float cc = 1.f, ss = 0.f;
        #pragma unroll
        for (int q = 0; q < 32; q++) {
            float2 y = Yp[q];
            re += y.x*cc + y.y*ss;
            im += y.y*cc - y.x*ss;
            float nc = cc*rc2 - ss*rs2;
            ss = ss*rc2 + cc*rs2;
            cc = nc;
        }
        Xt[(kxx*32 + kt)*3 + pp] = make_float2(re, im);
    }
    __syncthreads();
    for (int idx = tid; idx < 1024; idx += 384) {         // p-rfft + store
        int kxx = idx >> 6, r = idx & 63;
        int kt = r & 31, kz = r >> 5;
        const float2* Xp = Xt + (kxx*32 + kt)*3;
        float2 a0f = Xp[0], a1f = Xp[1], a2f = Xp[2];
        float2 rr;
        if (kz == 0) rr = make_float2(a0f.x + a1f.x + a2f.x, a0f.y + a1f.y + a2f.y);
        else rr = make_float2(a0f.x - 0.5f*(a1f.x + a2f.x) + S3*(a1f.y - a2f.y),
                              a0f.y - 0.5f*(a1f.y + a2f.y) - S3*(a1f.x - a2f.x));
        g_X[(size_t)((kt*16 + kxx)*2 + kz)*256 + bi] = rr;
    }
}

// ---------------- k3: per-mode complex GEMM (fp16 weights) ----------------
__global__ void k3_mix() {
    __shared__ float2 Xs[256];
    __shared__ float2 Ws[1024];
    int mode = blockIdx.x, tid = threadIdx.x;
    Xs[tid] = g_X[(size_t)mode*256 + tid];
    {
        uint4 wv = ((const uint4*)(g_Wh + (size_t)mode*1024))[tid];
        __half2 h;
        h = *reinterpret_cast<__half2*>(&wv.x); Ws[tid*4 + 0] = __half22float2(h);
        h = *reinterpret_cast<__half2*>(&wv.y); Ws[tid*4 + 1] = __half22float2(h);
        h = *reinterpret_cast<__half2*>(&wv.z); Ws[tid*4 + 2] = __half22float2(h);
        h = *reinterpret_cast<__half2*>(&wv.w); Ws[tid*4 + 3] = __half22float2(h);
    }
    __syncthreads();
    int b = tid >> 5, o = tid & 31;
    float re0=0, im0=0, re1=0, im1=0;
    #pragma unroll
    for (int i = 0; i < 32; i += 2) {
        float2 xv = Xs[b*32 + i];     float2 wv = Ws[i*32 + o];
        re0 += xv.x*wv.x - xv.y*wv.y; im0 += xv.x*wv.y + xv.y*wv.x;
        float2 xq = Xs[b*32 + i + 1]; float2 wq = Ws[(i+1)*32 + o];
        re1 += xq.x*wq.x - xq.y*wq.y; im1 += xq.x*wq.y + xq.y*wq.x;
    }
    int kz = mode & 1, kx = (mode >> 1) & 15, kt = mode >> 5;
    g_Y[(size_t)(((b*32 + o)*16 + kx)*32 + kt)*2 + kz] = make_float2(re0+re1, im0+im1);
}

// ---------------- kB: fused U-build + t-expand + x-expand -----------------
// grid 256 = bo; block 576 (18 warps), 2 blocks/SM
// dyn smem (f2): Y 1024 | U 1536 | Vq 6272 | Tsh 512 = 9344 f2 = 74752 B
__global__ void __launch_bounds__(576, 2) kB_inv(float* __restrict__ out) {
    extern __shared__ float2 smem[];
    float2* Y_sh = smem;                          // [kx*64 + kt*2 + kz]
    float2* U_sh = smem + 1024;                   // [kx*96 + kt*3 + p]
    ulonglong2* Vq = (ulonglong2*)(smem + 2560);  // [pr*49 + kx*3 + p] = (vx01, vy01)
    ulonglong2* Tsh = (ulonglong2*)(smem + 8832); // [c-1][q] c=1..4  (cc,ss packed)
    int bo = blockIdx.x, tid = threadIdx.x;

    for (int idx = tid; idx < 512; idx += 576)
        ((float4*)Y_sh)[idx] = ((const float4*)(g_Y + (size_t)bo*1024))[idx];
    for (int idx = tid; idx < 256; idx += 576)
        Tsh[idx] = ((const ulonglong2*)g_T5q)[64 + idx];       // rows kx=1..4
    __syncthreads();

    // B2: build U  (SC folds the fp16 x1024 weight scale)
    for (int idx = tid; idx < 1536; idx += 576) {
        int kx = idx / 96, r = idx - kx*96;
        int kt = r & 31, p = r >> 5;
        float2 y0 = Y_sh[kx*64 + kt*2], y1 = Y_sh[kx*64 + kt*2 + 1];
        float wx, wy;                          // 2 * e^{2 pi i p / 3}
        if (p == 0)      { wx = 2.f;  wy = 0.f; }
        else if (p == 1) { wx = -1.f; wy =  2.f*S3; }
        else             { wx = -1.f; wy = -2.f*S3; }
        const float SC = 1.f/100663296.f;      // 1/(128*256*3*1024)
        U_sh[kx*96 + kt*3 + p] = make_float2(SC*(y0.x + wx*y1.x - wy*y1.y),
                                             SC*(y0.y + wx*y1.y + wy*y1.x));
    }
    __syncthreads();

    // B3: t-expand radix-4 -> Vq via per-q Horner (no T4 loads)
    for (int idx = tid; idx < 1536; idx += 576) {
        int kx = idx / 96, r = idx - kx*96;
        int q = r & 31, p = r >> 5;
        float rs, rc;  sincospif((float)q * 0.0625f,   &rs, &rc);    // rho = e^{i pi q/16}
        float ts1, tc1; sincospif((float)q * 0.015625f, &ts1, &tc1); // tau = e^{i pi q/64}
        float r4s, r4c; sincospif((float)q * 0.25f,     &r4s, &r4c); // rho^4
        float kr, ki;                          // kappa = (-i)^q * rho^4
        switch (q & 3) {
            case 0: kr = r4c;  ki = r4s;  break;
            case 1: kr = r4s;  ki = -r4c; break;
            case 2: kr = -r4c; ki = -r4s; break;
            default:kr = -r4s; ki = r4c;  break;
        }
        float t2c = tc1*tc1 - ts1*ts1, t2s = 2.f*tc1*ts1;
        float t3c = t2c*tc1 - t2s*ts1, t3s = t2s*tc1 + t2c*ts1;
        const float2* Ub = U_sh + kx*96 + p;
        float Sx[4], Sy[4];
        #pragma unroll
        for (int c = 0; c < 4; c++) {
            float2 u = Ub[(c + 28)*3];
            float hx = u.x, hy = u.y;
            #pragma unroll
            for (int m = 6; m >= 4; m--) {
                u = Ub[(c + 4*m)*3];
                float nx = u.x + rc*hx - rs*hy;
                float ny = u.y + rc*hy + rs*hx;
                hx = nx; hy = ny;
            }
            float hix = hx, hiy = hy;
            u = Ub[(c + 12)*3];
            hx = u.x; hy = u.y;
            #pragma unroll
            for (int m = 2; m >= 0; m--) {
                u = Ub[(c + 4*m)*3];
                float nx = u.x + rc*hx - rs*hy;
                float ny = u.y + rc*hy + rs*hx;
                hx = nx; hy = ny;
            }
            float sx = hx + kr*hix - ki*hiy;
            float sy = hy + kr*hiy + ki*hix;
            if (c == 1)      { float tx = sx*tc1 - sy*ts1; sy = sx*ts1 + sy*tc1; sx = tx; }
            else if (c == 2) { float tx = sx*t2c - sy*t2s; sy = sx*t2s + sy*t2c; sx = tx; }
            else if (c == 3) { float tx = sx*t3c - sy*t3s; sy = sx*t3s + sy*t3c; sx = tx; }
            Sx[c] = sx; Sy[c] = sy;
        }
        float s0x = Sx[0], s0y = Sy[0], s1x = Sx[1], s1y = Sy[1];
        float s2x = Sx[2], s2y = Sy[2], s3x = Sx[3], s3y = Sy[3];
        float vr[4], vi[4];
        vr[0] = s0x+s1x+s2x+s3x; vi[0] = s0y+s1y+s2y+s3y;
        vr[1] = s0x-s1y-s2x+s3y; vi[1] = s0y+s1x-s2y-s3x;
        vr[2] = s0x-s1x+s2x-s3x; vi[2] = s0y-s1y+s2y-s3y;
        vr[3] = s0x+s1y-s2x-s3y; vi[3] = s0y-s1x-s2y+s3x;
        int h = q & 1;
        float* base = (float*)Vq;
        #pragma unroll
        for (int m = 0; m < 4; m++) {
            int pr = (q >> 1) + 16*m;
            int e4 = (pr*49 + kx*3 + p)*4;
            base[e4 + h]     = vr[m];
            base[e4 + 2 + h] = vi[m];
        }
    }
    __syncthreads();

    // B4: x-expand radix-4 via Horner (no in-loop twiddle loads)
    {
        int ee = tid % 192, prh = tid / 192;      // prh in 0..2 (576 = 3*192)
        int q = ee / 3, p = ee - q*3;
        ulonglong2 Rv = Tsh[192 + q];             // kx=4 row: phi = pi q/32
        u64 RC = Rv.x, RS = Rv.y;
        float2 rsf = u2f(RS);
        u64 NRS = pack2(-rsf.x, -rsf.y);
        float tc1 = u2f(Tsh[q].x).x,       ts1 = u2f(Tsh[q].y).x;
        float tc2 = u2f(Tsh[64 + q].x).x,  ts2 = u2f(Tsh[64 + q].y).x;
        float tc3 = u2f(Tsh[128 + q].x).x, ts3 = u2f(Tsh[128 + q].y).x;

        for (int pr = prh; pr < 64; pr += 3) {
            const ulonglong2* vrow = Vq + pr*49 + p;
            u64 W0x, W0y, W1x, W1y, W2x, W2y, W3x, W3y;
            { ulonglong2 v = vrow[12*3]; W0x = v.x; W0y = v.y; }
            { ulonglong2 v = vrow[13*3]; W1x = v.x; W1y = v.y; }
            { ulonglong2 v = vrow[14*3]; W2x = v.x; W2y = v.y; }
            { ulonglong2 v = vrow[15*3]; W3x = v.x; W3y = v.y; }
            #define HSTEP(c, jj) { \
                ulonglong2 v = vrow[((c) + 4*(jj))*3]; \
                u64 t_ = v.x; ffma2(t_, W##c##x, RC); ffma2(t_, W##c##y, NRS); \
                u64 u_ = v.y; ffma2(u_, W##c##x, RS); ffma2(u_, W##c##y, RC);  \
                W##c##x = t_; W##c##y = u_; }
            HSTEP(0, 2) HSTEP(1, 2) HSTEP(2, 2) HSTEP(3, 2)
            HSTEP(0, 1) HSTEP(1, 1) HSTEP(2, 1) HSTEP(3, 1)
            HSTEP(0, 0) HSTEP(1, 0) HSTEP(2, 0) HSTEP(3, 0)
            #undef HSTEP
            float2 W0xf = u2f(W0x);
            float2 W1xf = u2f(W1x), W1yf = u2f(W1y);
            float2 W2xf = u2f(W2x), W2yf = u2f(W2y);
            float2 W3xf = u2f(W3x), W3yf = u2f(W3y);
            float* r0 = out + ((size_t)bo*128 + pr*2)*768;
            float* r1 = r0 + 768;
            #pragma unroll
            for (int h = 0; h < 2; h++) {
                float w0x = h ? W0xf.y : W0xf.x;
                float w1x = h ? W1xf.y : W1xf.x, w1y = h ? W1yf.y : W1yf.x;
                float w2x = h ? W2xf.y : W2xf.x, w2y = h ? W2yf.y : W2yf.x;
                float w3x = h ? W3xf.y : W3xf.x, w3y = h ? W3yf.y : W3yf.x;
                float tr0 = w0x;
                float tr1 = w1x*tc1 - w1y*ts1;
                float ti1 = w1x*ts1 + w1y*tc1;
                float tr2 = w2x*tc2 - w2y*ts2;
                float tr3 = w3x*tc3 - w3y*ts3;
                float ti3 = w3x*ts3 + w3y*tc3;
                float ev = tr0 + tr2, fv = tr0 - tr2;
                float g1 = tr1 + tr3, dti = ti3 - ti1;
                float* row = h ? r1 : r0;
                row[(q      )*3 + p] = ev + g1;
                row[(q + 64 )*3 + p] = fv + dti;
                row[(q + 128)*3 + p] = ev - g1;
                row[(q + 192)*3 + p] = fv - dti;
            }
        }
    }
}

extern "C" void kernel_launch(void* const* d_in, const int* in_sizes, int n_in,
                              void* d_out, int out_size) {
    const float* x    = (const float*)d_in[0];
    const float* w1re = (const float*)d_in[1];
    const float* w1im = (const float*)d_in[2];
    const float* w2re = (const float*)d_in[3];
    const float* w2im = (const float*)d_in[4];
    float* out = (float*)d_out;

    static int attr_done = 0;
    if (!attr_done) {
        cudaFuncSetAttribute(kAC_fwd, cudaFuncAttributeMaxDynamicSharedMemorySize, 98816);
        cudaFuncSetAttribute(kB_inv, cudaFuncAttributeMaxDynamicSharedMemorySize, 74752);
        attr_done = 1;
    }

    kAC_fwd<<<513, 384, 98816>>>(x, w1re, w1im, w2re, w2im);
    k3_mix<<<1024, 256>>>();
    kB_inv<<<256, 576, 74752>>>(out);
}